// round 1
// baseline (speedup 1.0000x reference)
#include <cuda_runtime.h>
#include <mma.h>
#include <math.h>
#include <stdint.h>

using namespace nvcuda;

// ---------------- problem constants ----------------
#define BATCH 2
#define SEQ   2048
#define HID   1024
#define NHEAD 8
#define HDIM  128
#define FF    4096
#define MTOT  (BATCH*SEQ)      // 4096
#define LN_EPS 1e-5f

// ---------------- scratch (static device, no allocs) ----------------
__device__ float g_h  [MTOT*HID];
__device__ float g_q  [MTOT*HID];
__device__ float g_k  [MTOT*HID];
__device__ float g_v  [MTOT*HID];
__device__ float g_y  [MTOT*HID];
__device__ float g_x2 [MTOT*HID];
__device__ float g_h2 [MTOT*HID];
__device__ float g_m1 [(size_t)MTOT*FF];
__device__ float g_p  [(size_t)BATCH*NHEAD*SEQ*SEQ];   // 268 MB scores/probs

// ---------------- block reduce helpers ----------------
__device__ __forceinline__ float warpSum(float v){
#pragma unroll
    for (int o=16;o;o>>=1) v += __shfl_xor_sync(0xffffffffu, v, o);
    return v;
}
__device__ __forceinline__ float warpMax(float v){
#pragma unroll
    for (int o=16;o;o>>=1) v = fmaxf(v, __shfl_xor_sync(0xffffffffu, v, o));
    return v;
}
__device__ __forceinline__ float blockSum(float v, float* red){
    __syncthreads();
    int lane = threadIdx.x & 31, wid = threadIdx.x >> 5;
    v = warpSum(v);
    if (lane==0) red[wid] = v;
    __syncthreads();
    if (wid==0){
        float r = (lane < (int)(blockDim.x>>5)) ? red[lane] : 0.f;
        r = warpSum(r);
        if (lane==0) red[0] = r;
    }
    __syncthreads();
    return red[0];
}
__device__ __forceinline__ float blockMax(float v, float* red){
    __syncthreads();
    int lane = threadIdx.x & 31, wid = threadIdx.x >> 5;
    v = warpMax(v);
    if (lane==0) red[wid] = v;
    __syncthreads();
    if (wid==0){
        float r = (lane < (int)(blockDim.x>>5)) ? red[lane] : -1e30f;
        r = warpMax(r);
        if (lane==0) red[0] = r;
    }
    __syncthreads();
    return red[0];
}

// ---------------- layernorm ----------------
__global__ void __launch_bounds__(256) ln_kernel(const float* __restrict__ x,
                                                 const float* __restrict__ g,
                                                 const float* __restrict__ b,
                                                 float* __restrict__ out)
{
    __shared__ float red[32];
    int row = blockIdx.x;
    const float* xr = x + (size_t)row*HID;
    float v[4];
    float s = 0.f;
#pragma unroll
    for (int t=0;t<4;t++){ v[t] = xr[threadIdx.x + t*256]; s += v[t]; }
    s = blockSum(s, red);
    float mu = s * (1.f/HID);
    float s2 = 0.f;
#pragma unroll
    for (int t=0;t<4;t++){ float d = v[t]-mu; s2 += d*d; }
    s2 = blockSum(s2, red);
    float rstd = rsqrtf(s2*(1.f/HID) + LN_EPS);
    float* orow = out + (size_t)row*HID;
#pragma unroll
    for (int t=0;t<4;t++){
        int c = threadIdx.x + t*256;
        orow[c] = (v[t]-mu)*rstd*g[c] + b[c];
    }
}

// ---------------- causal softmax (in place on g_p) ----------------
__global__ void __launch_bounds__(256) softmax_kernel(float* __restrict__ P)
{
    __shared__ float red[32];
    int i  = blockIdx.x;          // query row
    int bh = blockIdx.y;
    float* row = P + ((size_t)bh*SEQ + i)*SEQ;
    int L    = i + 1;                       // valid (causal) length
    int Lpad = ((i>>7)+1)<<7;               // zero-fill up to this q-tile's K boundary

    float m = -1e30f;
    for (int j=threadIdx.x; j<L; j+=256) m = fmaxf(m, row[j]);
    m = blockMax(m, red);

    float s = 0.f;
    for (int j=threadIdx.x; j<L; j+=256) s += __expf(row[j]-m);
    s = blockSum(s, red);
    float inv = 1.f/s;

    for (int j=threadIdx.x; j<Lpad; j+=256)
        row[j] = (j < L) ? __expf(row[j]-m)*inv : 0.f;
}

// ---------------- generic tf32 tensor-core GEMM ----------------
// C[M,N] = epilogue( scale * A[M,K] @ op(B) )  with optional bias / residual / GELU
// BT=false : B is row-major [K,N] (ldb)
// BT=true  : B is row-major [N,K] (ldb), used transposed (i.e. C = A @ B^T)
// CAUSAL   : skip tiles with bx>by, and clamp K to (by+1)*BM
// batching : operand base offset for blockIdx.z = (z>>3)*so + (z&7)*si

enum { EPI_SCALE=0, EPI_BIAS=1, EPI_BIAS_RES=2, EPI_BIAS_GELU=3 };

constexpr int BM = 128, BN = 128, BK = 16;
constexpr int LDAS = BK + 8;     // 24
constexpr int LDBS = BN + 8;     // 136
constexpr int BS_ELEMS = (BN*LDAS > BK*LDBS) ? BN*LDAS : BK*LDBS;

template<int EPI, bool BT, bool CAUSAL>
__global__ void __launch_bounds__(256) gemm_kernel(
    const float* __restrict__ A, const float* __restrict__ B,
    const float* __restrict__ bias, const float* __restrict__ res,
    float* __restrict__ C,
    int M, int N, int K,
    int lda, int ldb, int ldc,
    long long soA, long long siA,
    long long soB, long long siB,
    long long soC, long long siC,
    float scale)
{
    int bx = blockIdx.x, by = blockIdx.y, bz = blockIdx.z;
    if (CAUSAL && bx > by) return;
    int Keff = K;
    if (CAUSAL){ int kl = (by+1)*BM; if (kl < Keff) Keff = kl; }

    long long offA = (long long)(bz>>3)*soA + (long long)(bz&7)*siA;
    long long offB = (long long)(bz>>3)*soB + (long long)(bz&7)*siB;
    long long offC = (long long)(bz>>3)*soC + (long long)(bz&7)*siC;
    A += offA; B += offB; C += offC;
    const float* resp = (EPI==EPI_BIAS_RES) ? (res + offC) : nullptr;

    __shared__ __align__(16) float As[BM*LDAS];
    __shared__ __align__(16) float Bs[BS_ELEMS];
    __shared__ __align__(16) float stage[8][16*20];

    int tid  = threadIdx.x;
    int wid  = tid >> 5;
    int lane = tid & 31;
    int row0 = by*BM, col0 = bx*BN;
    int wr = (wid>>2)*64;         // warp row offset in block tile
    int wc = (wid&3)*32;          // warp col offset

    wmma::fragment<wmma::accumulator,16,16,8,float> acc[4][2];
#pragma unroll
    for (int i=0;i<4;i++)
#pragma unroll
        for (int j=0;j<2;j++) wmma::fill_fragment(acc[i][j], 0.f);

    for (int k0=0; k0<Keff; k0+=BK){
        // load A tile: 128 x 16
#pragma unroll
        for (int p=0;p<2;p++){
            int idx = tid + p*256;       // one float4 per idx
            int r   = idx >> 2;
            int c4  = (idx & 3) * 4;
            float4 v = *reinterpret_cast<const float4*>(A + (size_t)(row0+r)*lda + k0 + c4);
            float* d = &As[r*LDAS + c4];
            d[0] = wmma::__float_to_tf32(v.x);
            d[1] = wmma::__float_to_tf32(v.y);
            d[2] = wmma::__float_to_tf32(v.z);
            d[3] = wmma::__float_to_tf32(v.w);
        }
        if (BT){
            // B tile: 128 (output cols) x 16 (k)
#pragma unroll
            for (int p=0;p<2;p++){
                int idx = tid + p*256;
                int r   = idx >> 2;
                int c4  = (idx & 3) * 4;
                float4 v = *reinterpret_cast<const float4*>(B + (size_t)(col0+r)*ldb + k0 + c4);
                float* d = &Bs[r*LDAS + c4];
                d[0] = wmma::__float_to_tf32(v.x);
                d[1] = wmma::__float_to_tf32(v.y);
                d[2] = wmma::__float_to_tf32(v.z);
                d[3] = wmma::__float_to_tf32(v.w);
            }
        } else {
            // B tile: 16 (k) x 128 (output cols)
#pragma unroll
            for (int p=0;p<2;p++){
                int idx = tid + p*256;
                int r   = idx >> 5;
                int c4  = (idx & 31) * 4;
                float4 v = *reinterpret_cast<const float4*>(B + (size_t)(k0+r)*ldb + col0 + c4);
                float* d = &Bs[r*LDBS + c4];
                d[0] = wmma::__float_to_tf32(v.x);
                d[1] = wmma::__float_to_tf32(v.y);
                d[2] = wmma::__float_to_tf32(v.z);
                d[3] = wmma::__float_to_tf32(v.w);
            }
        }
        __syncthreads();

#pragma unroll
        for (int kk=0; kk<BK; kk+=8){
            wmma::fragment<wmma::matrix_a,16,16,8,wmma::precision::tf32,wmma::row_major> af[4];
#pragma unroll
            for (int i=0;i<4;i++)
                wmma::load_matrix_sync(af[i], &As[(wr+i*16)*LDAS + kk], LDAS);
            if constexpr (BT){
                wmma::fragment<wmma::matrix_b,16,16,8,wmma::precision::tf32,wmma::col_major> bf[2];
#pragma unroll
                for (int j=0;j<2;j++)
                    wmma::load_matrix_sync(bf[j], &Bs[(wc+j*16)*LDAS + kk], LDAS);
#pragma unroll
                for (int i=0;i<4;i++)
#pragma unroll
                    for (int j=0;j<2;j++)
                        wmma::mma_sync(acc[i][j], af[i], bf[j], acc[i][j]);
            } else {
                wmma::fragment<wmma::matrix_b,16,16,8,wmma::precision::tf32,wmma::row_major> bf[2];
#pragma unroll
                for (int j=0;j<2;j++)
                    wmma::load_matrix_sync(bf[j], &Bs[kk*LDBS + wc + j*16], LDBS);
#pragma unroll
                for (int i=0;i<4;i++)
#pragma unroll
                    for (int j=0;j<2;j++)
                        wmma::mma_sync(acc[i][j], af[i], bf[j], acc[i][j]);
            }
        }
        __syncthreads();
    }

    // epilogue: stage each 16x16 fragment through per-warp shared, fuse bias/res/gelu
#pragma unroll
    for (int i=0;i<4;i++){
#pragma unroll
        for (int j=0;j<2;j++){
            wmma::store_matrix_sync(&stage[wid][0], acc[i][j], 20, wmma::mem_row_major);
            __syncwarp();
#pragma unroll
            for (int e=lane; e<256; e+=32){
                int r  = e >> 4, cc = e & 15;
                int gr = row0 + wr + i*16 + r;
                int gc = col0 + wc + j*16 + cc;
                float v = stage[wid][r*20 + cc] * scale;
                if (EPI >= EPI_BIAS)      v += bias[gc];
                if (EPI == EPI_BIAS_RES)  v += resp[(size_t)gr*ldc + gc];
                if (EPI == EPI_BIAS_GELU) v = 0.5f*v*(1.f + erff(v*0.70710678118654752f));
                C[(size_t)gr*ldc + gc] = v;
            }
            __syncwarp();
        }
    }
}

// ---------------- launch ----------------
extern "C" void kernel_launch(void* const* d_in, const int* in_sizes, int n_in,
                              void* d_out, int out_size)
{
    const float* x    = (const float*)d_in[0];
    const float* ln1g = (const float*)d_in[1];
    const float* ln1b = (const float*)d_in[2];
    const float* ln2g = (const float*)d_in[3];
    const float* ln2b = (const float*)d_in[4];
    const float* Wq   = (const float*)d_in[5];
    const float* bq   = (const float*)d_in[6];
    const float* Wk   = (const float*)d_in[7];
    const float* bk   = (const float*)d_in[8];
    const float* Wv   = (const float*)d_in[9];
    const float* bv   = (const float*)d_in[10];
    const float* Wo   = (const float*)d_in[11];
    const float* bo   = (const float*)d_in[12];
    const float* W1   = (const float*)d_in[13];
    const float* b1   = (const float*)d_in[14];
    const float* W2   = (const float*)d_in[15];
    const float* b2   = (const float*)d_in[16];
    float* out = (float*)d_out;

    void *ph, *pq, *pk, *pv, *py, *px2, *ph2, *pm1, *pp;
    cudaGetSymbolAddress(&ph,  g_h);
    cudaGetSymbolAddress(&pq,  g_q);
    cudaGetSymbolAddress(&pk,  g_k);
    cudaGetSymbolAddress(&pv,  g_v);
    cudaGetSymbolAddress(&py,  g_y);
    cudaGetSymbolAddress(&px2, g_x2);
    cudaGetSymbolAddress(&ph2, g_h2);
    cudaGetSymbolAddress(&pm1, g_m1);
    cudaGetSymbolAddress(&pp,  g_p);
    float* h  = (float*)ph;   float* q  = (float*)pq;  float* k  = (float*)pk;
    float* v  = (float*)pv;   float* y  = (float*)py;  float* x2 = (float*)px2;
    float* h2 = (float*)ph2;  float* m1 = (float*)pm1; float* P  = (float*)pp;

    const float SCORE_SCALE = 0.08838834764831845f; // 1/sqrt(128)

    // 1) LN1
    ln_kernel<<<MTOT, 256>>>(x, ln1g, ln1b, h);

    // 2) Q, K, V projections  [4096,1024] @ [1024,1024] + bias
    dim3 gP(HID/BN, MTOT/BM, 1);
    gemm_kernel<EPI_BIAS,false,false><<<gP,256>>>(h, Wq, bq, nullptr, q,
        MTOT, HID, HID, HID, HID, HID, 0,0, 0,0, 0,0, 1.f);
    gemm_kernel<EPI_BIAS,false,false><<<gP,256>>>(h, Wk, bk, nullptr, k,
        MTOT, HID, HID, HID, HID, HID, 0,0, 0,0, 0,0, 1.f);
    gemm_kernel<EPI_BIAS,false,false><<<gP,256>>>(h, Wv, bv, nullptr, v,
        MTOT, HID, HID, HID, HID, HID, 0,0, 0,0, 0,0, 1.f);

    // 3) scores = q @ k^T / sqrt(HD), per (b,h); causal tile skip
    {
        dim3 g(SEQ/BN, SEQ/BM, BATCH*NHEAD);
        long long sA_o = (long long)SEQ*HID, sA_i = HDIM;                 // q/k head offsets
        long long sC_o = 8LL*SEQ*SEQ,        sC_i = (long long)SEQ*SEQ;   // z*S*S
        gemm_kernel<EPI_SCALE,true,true><<<g,256>>>(q, k, nullptr, nullptr, P,
            SEQ, SEQ, HDIM, HID, HID, SEQ,
            sA_o, sA_i, sA_o, sA_i, sC_o, sC_i, SCORE_SCALE);
    }

    // 4) causal softmax rows (zeroes the intra-tile upper triangle)
    softmax_kernel<<<dim3(SEQ, BATCH*NHEAD), 256>>>(P);

    // 5) y = P @ V, per (b,h); K truncated per q-tile
    {
        dim3 g(1, SEQ/BM, BATCH*NHEAD);
        long long sA_o = 8LL*SEQ*SEQ, sA_i = (long long)SEQ*SEQ;
        long long sB_o = (long long)SEQ*HID, sB_i = HDIM;
        gemm_kernel<EPI_SCALE,false,true><<<g,256>>>(P, v, nullptr, nullptr, y,
            SEQ, HDIM, SEQ, SEQ, HID, HID,
            sA_o, sA_i, sB_o, sB_i, sB_o, sB_i, 1.f);
    }

    // 6) x2 = x + y @ Wo + bo
    gemm_kernel<EPI_BIAS_RES,false,false><<<gP,256>>>(y, Wo, bo, x, x2,
        MTOT, HID, HID, HID, HID, HID, 0,0, 0,0, 0,0, 1.f);

    // 7) LN2
    ln_kernel<<<MTOT, 256>>>(x2, ln2g, ln2b, h2);

    // 8) m1 = gelu(h2 @ W1 + b1)   [4096,1024]@[1024,4096]
    {
        dim3 g(FF/BN, MTOT/BM, 1);
        gemm_kernel<EPI_BIAS_GELU,false,false><<<g,256>>>(h2, W1, b1, nullptr, m1,
            MTOT, FF, HID, HID, FF, FF, 0,0, 0,0, 0,0, 1.f);
    }

    // 9) out = x2 + m1 @ W2 + b2   [4096,4096]@[4096,1024]
    gemm_kernel<EPI_BIAS_RES,false,false><<<gP,256>>>(m1, W2, b2, x2, out,
        MTOT, HID, FF, FF, HID, HID, 0,0, 0,0, 0,0, 1.f);
}

// round 2
// speedup vs baseline: 1.2407x; 1.2407x over previous
#include <cuda_runtime.h>
#include <mma.h>
#include <math.h>
#include <stdint.h>

using namespace nvcuda;

// ---------------- problem constants ----------------
#define BATCH 2
#define SEQ   2048
#define HID   1024
#define NHEAD 8
#define HDIM  128
#define FF    4096
#define MTOT  (BATCH*SEQ)      // 4096
#define LN_EPS 1e-5f

// ---------------- scratch (static device, no allocs) ----------------
__device__ float g_h   [MTOT*HID];
__device__ float g_qkv [(size_t)MTOT*3*HID];          // packed q|k|v, 50 MB
__device__ float g_y   [MTOT*HID];
__device__ float g_x2  [MTOT*HID];
__device__ float g_h2  [MTOT*HID];
__device__ float g_m1  [(size_t)MTOT*FF];
__device__ float g_p   [(size_t)BATCH*NHEAD*SEQ*SEQ]; // 268 MB scores/probs
__device__ float g_wqkv[(size_t)HID*3*HID];           // packed Wq|Wk|Wv
__device__ float g_bqkv[3*HID];

// ---------------- cp.async helpers ----------------
__device__ __forceinline__ void cp_async16(void* smem_dst, const void* gmem_src){
    uint32_t s = (uint32_t)__cvta_generic_to_shared(smem_dst);
    asm volatile("cp.async.cg.shared.global [%0], [%1], 16;\n" :: "r"(s), "l"(gmem_src));
}
__device__ __forceinline__ void cp_commit(){
    asm volatile("cp.async.commit_group;\n");
}
template<int N>
__device__ __forceinline__ void cp_wait(){
    asm volatile("cp.async.wait_group %0;\n" :: "n"(N));
}

// ---------------- block reduce helpers ----------------
__device__ __forceinline__ float warpSum(float v){
#pragma unroll
    for (int o=16;o;o>>=1) v += __shfl_xor_sync(0xffffffffu, v, o);
    return v;
}
__device__ __forceinline__ float warpMax(float v){
#pragma unroll
    for (int o=16;o;o>>=1) v = fmaxf(v, __shfl_xor_sync(0xffffffffu, v, o));
    return v;
}
__device__ __forceinline__ float blockSum(float v, float* red){
    __syncthreads();
    int lane = threadIdx.x & 31, wid = threadIdx.x >> 5;
    v = warpSum(v);
    if (lane==0) red[wid] = v;
    __syncthreads();
    if (wid==0){
        float r = (lane < (int)(blockDim.x>>5)) ? red[lane] : 0.f;
        r = warpSum(r);
        if (lane==0) red[0] = r;
    }
    __syncthreads();
    return red[0];
}
__device__ __forceinline__ float blockMax(float v, float* red){
    __syncthreads();
    int lane = threadIdx.x & 31, wid = threadIdx.x >> 5;
    v = warpMax(v);
    if (lane==0) red[wid] = v;
    __syncthreads();
    if (wid==0){
        float r = (lane < (int)(blockDim.x>>5)) ? red[lane] : -1e30f;
        r = warpMax(r);
        if (lane==0) red[0] = r;
    }
    __syncthreads();
    return red[0];
}

// ---------------- pack QKV weights ----------------
__global__ void __launch_bounds__(256) pack_qkv_kernel(
    const float* __restrict__ Wq, const float* __restrict__ Wk, const float* __restrict__ Wv,
    const float* __restrict__ bq, const float* __restrict__ bk, const float* __restrict__ bv,
    float* __restrict__ W, float* __restrict__ b)
{
    size_t i = (size_t)blockIdx.x*256 + threadIdx.x;
    size_t total = (size_t)HID*3*HID;
    for (size_t idx = i; idx < total; idx += (size_t)gridDim.x*256){
        size_t k = idx / (3*HID);
        int    n = (int)(idx % (3*HID));
        float v;
        if      (n <   HID) v = Wq[k*HID + n];
        else if (n < 2*HID) v = Wk[k*HID + (n-HID)];
        else                v = Wv[k*HID + (n-2*HID)];
        W[idx] = v;
    }
    if (i < 3*HID){
        int n = (int)i;
        b[n] = (n < HID) ? bq[n] : (n < 2*HID ? bk[n-HID] : bv[n-2*HID]);
    }
}

// ---------------- layernorm ----------------
__global__ void __launch_bounds__(256) ln_kernel(const float* __restrict__ x,
                                                 const float* __restrict__ g,
                                                 const float* __restrict__ b,
                                                 float* __restrict__ out)
{
    __shared__ float red[32];
    int row = blockIdx.x;
    const float* xr = x + (size_t)row*HID;
    float v[4];
    float s = 0.f;
#pragma unroll
    for (int t=0;t<4;t++){ v[t] = xr[threadIdx.x + t*256]; s += v[t]; }
    s = blockSum(s, red);
    float mu = s * (1.f/HID);
    float s2 = 0.f;
#pragma unroll
    for (int t=0;t<4;t++){ float d = v[t]-mu; s2 += d*d; }
    s2 = blockSum(s2, red);
    float rstd = rsqrtf(s2*(1.f/HID) + LN_EPS);
    float* orow = out + (size_t)row*HID;
#pragma unroll
    for (int t=0;t<4;t++){
        int c = threadIdx.x + t*256;
        orow[c] = (v[t]-mu)*rstd*g[c] + b[c];
    }
}

// ---------------- causal softmax (in place on g_p) ----------------
__global__ void __launch_bounds__(256) softmax_kernel(float* __restrict__ P)
{
    __shared__ float red[32];
    int i  = blockIdx.x;          // query row
    int bh = blockIdx.y;
    float* row = P + ((size_t)bh*SEQ + i)*SEQ;
    int L    = i + 1;
    int Lpad = ((i>>7)+1)<<7;

    float m = -1e30f;
    for (int j=threadIdx.x; j<L; j+=256) m = fmaxf(m, row[j]);
    m = blockMax(m, red);

    float s = 0.f;
    for (int j=threadIdx.x; j<L; j+=256) s += __expf(row[j]-m);
    s = blockSum(s, red);
    float inv = 1.f/s;

    for (int j=threadIdx.x; j<Lpad; j+=256)
        row[j] = (j < L) ? __expf(row[j]-m)*inv : 0.f;
}

// ---------------- pipelined tf32 tensor-core GEMM ----------------
// C[M,N] = epi( scale * A[M,K] @ op(B) ), 128x128 tile, BK=32, 3-stage cp.async
enum { EPI_SCALE=0, EPI_BIAS=1, EPI_BIAS_RES=2, EPI_BIAS_GELU=3 };

constexpr int BM = 128, BN = 128, BK = 32;
constexpr int STAGES = 3;
constexpr int LDA_S = BK + 4;            // 36 (x4B = 144, 16B-aligned rows)
constexpr int LDB_S = BN + 4;            // 132
constexpr int A_STG = BM * LDA_S;        // 4608 floats
constexpr int B_STG = (BK*LDB_S > BM*LDA_S) ? BK*LDB_S : BM*LDA_S; // 4608
constexpr size_t SMEM_BYTES = (size_t)STAGES * (A_STG + B_STG) * 4;

template<int EPI, bool BT, bool CAUSAL>
__global__ void __launch_bounds__(256) gemm_kernel(
    const float* __restrict__ A, const float* __restrict__ B,
    const float* __restrict__ bias, const float* __restrict__ res,
    float* __restrict__ C,
    int M, int N, int K,
    int lda, int ldb, int ldc,
    long long soA, long long siA,
    long long soB, long long siB,
    long long soC, long long siC,
    float scale)
{
    int bx = blockIdx.x, by = blockIdx.y, bz = blockIdx.z;
    if (CAUSAL && bx > by) return;
    int Keff = K;
    if (CAUSAL){ int kl = (by+1)*BM; if (kl < Keff) Keff = kl; }
    int nk = Keff / BK;

    long long offA = (long long)(bz>>3)*soA + (long long)(bz&7)*siA;
    long long offB = (long long)(bz>>3)*soB + (long long)(bz&7)*siB;
    long long offC = (long long)(bz>>3)*soC + (long long)(bz&7)*siC;
    A += offA; B += offB; C += offC;
    const float* resp = (EPI==EPI_BIAS_RES) ? (res + offC) : nullptr;

    extern __shared__ float smem[];
    float* As = smem;
    float* Bs = smem + (size_t)STAGES * A_STG;

    int tid  = threadIdx.x;
    int wid  = tid >> 5;
    int lane = tid & 31;
    int row0 = by*BM, col0 = bx*BN;
    int wr = (wid>>2)*64;
    int wc = (wid&3)*32;

    wmma::fragment<wmma::accumulator,16,16,8,float> acc[4][2];
#pragma unroll
    for (int i=0;i<4;i++)
#pragma unroll
        for (int j=0;j<2;j++) wmma::fill_fragment(acc[i][j], 0.f);

    // --- tile loaders: 1024 16B chunks each, 4 per thread ---
    auto load_tile = [&](int kt, int buf){
        int k0 = kt*BK;
        float* as = As + buf*A_STG;
        const float* Ab = A + (size_t)row0*lda + k0;
#pragma unroll
        for (int p=0;p<4;p++){
            int c  = tid + p*256;
            int r  = c >> 3;
            int q4 = (c & 7) * 4;
            cp_async16(as + r*LDA_S + q4, Ab + (size_t)r*lda + q4);
        }
        float* bs = Bs + buf*B_STG;
        if (BT){
            const float* Bb = B + (size_t)col0*ldb + k0;
#pragma unroll
            for (int p=0;p<4;p++){
                int c  = tid + p*256;
                int r  = c >> 3;
                int q4 = (c & 7) * 4;
                cp_async16(bs + r*LDA_S + q4, Bb + (size_t)r*ldb + q4);
            }
        } else {
            const float* Bb = B + (size_t)k0*ldb + col0;
#pragma unroll
            for (int p=0;p<4;p++){
                int c  = tid + p*256;
                int r  = c >> 5;
                int q4 = (c & 31) * 4;
                cp_async16(bs + r*LDB_S + q4, Bb + (size_t)r*ldb + q4);
            }
        }
    };

    auto compute = [&](int buf){
        const float* as = As + buf*A_STG;
        const float* bs = Bs + buf*B_STG;
#pragma unroll
        for (int kk=0; kk<BK; kk+=8){
            wmma::fragment<wmma::matrix_a,16,16,8,wmma::precision::tf32,wmma::row_major> af[4];
#pragma unroll
            for (int i=0;i<4;i++)
                wmma::load_matrix_sync(af[i], as + (wr+i*16)*LDA_S + kk, LDA_S);
            if constexpr (BT){
                wmma::fragment<wmma::matrix_b,16,16,8,wmma::precision::tf32,wmma::col_major> bf[2];
#pragma unroll
                for (int j=0;j<2;j++)
                    wmma::load_matrix_sync(bf[j], bs + (wc+j*16)*LDA_S + kk, LDA_S);
#pragma unroll
                for (int i=0;i<4;i++)
#pragma unroll
                    for (int j=0;j<2;j++)
                        wmma::mma_sync(acc[i][j], af[i], bf[j], acc[i][j]);
            } else {
                wmma::fragment<wmma::matrix_b,16,16,8,wmma::precision::tf32,wmma::row_major> bf[2];
#pragma unroll
                for (int j=0;j<2;j++)
                    wmma::load_matrix_sync(bf[j], bs + kk*LDB_S + wc + j*16, LDB_S);
#pragma unroll
                for (int i=0;i<4;i++)
#pragma unroll
                    for (int j=0;j<2;j++)
                        wmma::mma_sync(acc[i][j], af[i], bf[j], acc[i][j]);
            }
        }
    };

    // --- prologue: preload STAGES-1 stages ---
#pragma unroll
    for (int s=0; s<STAGES-1; s++){
        if (s < nk) load_tile(s, s);
        cp_commit();
    }

    // --- mainloop ---
    for (int kt=0; kt<nk; kt++){
        cp_wait<STAGES-2>();
        __syncthreads();
        int pre = kt + STAGES - 1;
        if (pre < nk) load_tile(pre, pre % STAGES);
        cp_commit();
        compute(kt % STAGES);
    }

    // --- epilogue: stage fragments through shared (reuse As) ---
    __syncthreads();
    float* epi = smem + (size_t)wid * 320;     // 16x20 per warp
#pragma unroll
    for (int i=0;i<4;i++){
#pragma unroll
        for (int j=0;j<2;j++){
            wmma::store_matrix_sync(epi, acc[i][j], 20, wmma::mem_row_major);
            __syncwarp();
#pragma unroll
            for (int e=lane; e<256; e+=32){
                int r  = e >> 4, cc = e & 15;
                int gr = row0 + wr + i*16 + r;
                int gc = col0 + wc + j*16 + cc;
                float v = epi[r*20 + cc] * scale;
                if (EPI >= EPI_BIAS)      v += bias[gc];
                if (EPI == EPI_BIAS_RES)  v += resp[(size_t)gr*ldc + gc];
                if (EPI == EPI_BIAS_GELU) v = 0.5f*v*(1.f + erff(v*0.70710678118654752f));
                C[(size_t)gr*ldc + gc] = v;
            }
            __syncwarp();
        }
    }
}

// ---------------- launch ----------------
extern "C" void kernel_launch(void* const* d_in, const int* in_sizes, int n_in,
                              void* d_out, int out_size)
{
    const float* x    = (const float*)d_in[0];
    const float* ln1g = (const float*)d_in[1];
    const float* ln1b = (const float*)d_in[2];
    const float* ln2g = (const float*)d_in[3];
    const float* ln2b = (const float*)d_in[4];
    const float* Wq   = (const float*)d_in[5];
    const float* bq   = (const float*)d_in[6];
    const float* Wk   = (const float*)d_in[7];
    const float* bk   = (const float*)d_in[8];
    const float* Wv   = (const float*)d_in[9];
    const float* bv   = (const float*)d_in[10];
    const float* Wo   = (const float*)d_in[11];
    const float* bo   = (const float*)d_in[12];
    const float* W1   = (const float*)d_in[13];
    const float* b1   = (const float*)d_in[14];
    const float* W2   = (const float*)d_in[15];
    const float* b2   = (const float*)d_in[16];
    float* out = (float*)d_out;

    void *ph, *pqkv, *py, *px2, *ph2, *pm1, *pp, *pw, *pb;
    cudaGetSymbolAddress(&ph,   g_h);
    cudaGetSymbolAddress(&pqkv, g_qkv);
    cudaGetSymbolAddress(&py,   g_y);
    cudaGetSymbolAddress(&px2,  g_x2);
    cudaGetSymbolAddress(&ph2,  g_h2);
    cudaGetSymbolAddress(&pm1,  g_m1);
    cudaGetSymbolAddress(&pp,   g_p);
    cudaGetSymbolAddress(&pw,   g_wqkv);
    cudaGetSymbolAddress(&pb,   g_bqkv);
    float* h   = (float*)ph;   float* qkv = (float*)pqkv;
    float* y   = (float*)py;   float* x2  = (float*)px2;
    float* h2  = (float*)ph2;  float* m1  = (float*)pm1;
    float* P   = (float*)pp;   float* Wqkv= (float*)pw;  float* bqkv = (float*)pb;

    // raise dynamic smem limits (no-op after first call)
    static bool attr_done = false;
    if (!attr_done){
        cudaFuncSetAttribute(gemm_kernel<EPI_BIAS,false,false>,      cudaFuncAttributeMaxDynamicSharedMemorySize, (int)SMEM_BYTES);
        cudaFuncSetAttribute(gemm_kernel<EPI_SCALE,true,true>,       cudaFuncAttributeMaxDynamicSharedMemorySize, (int)SMEM_BYTES);
        cudaFuncSetAttribute(gemm_kernel<EPI_SCALE,false,true>,      cudaFuncAttributeMaxDynamicSharedMemorySize, (int)SMEM_BYTES);
        cudaFuncSetAttribute(gemm_kernel<EPI_BIAS_RES,false,false>,  cudaFuncAttributeMaxDynamicSharedMemorySize, (int)SMEM_BYTES);
        cudaFuncSetAttribute(gemm_kernel<EPI_BIAS_GELU,false,false>, cudaFuncAttributeMaxDynamicSharedMemorySize, (int)SMEM_BYTES);
        attr_done = true;
    }

    const float SCORE_SCALE = 0.08838834764831845f; // 1/sqrt(128)

    // 0) pack QKV weights/bias
    pack_qkv_kernel<<<1024, 256>>>(Wq, Wk, Wv, bq, bk, bv, Wqkv, bqkv);

    // 1) LN1
    ln_kernel<<<MTOT, 256>>>(x, ln1g, ln1b, h);

    // 2) packed QKV projection: [4096,1024]@[1024,3072]+bias
    {
        dim3 g(3*HID/BN, MTOT/BM, 1);
        gemm_kernel<EPI_BIAS,false,false><<<g,256,SMEM_BYTES>>>(h, Wqkv, bqkv, nullptr, qkv,
            MTOT, 3*HID, HID, HID, 3*HID, 3*HID, 0,0, 0,0, 0,0, 1.f);
    }

    // 3) scores = q @ k^T / sqrt(HD); q at col 0, k at col HID within packed qkv
    {
        dim3 g(SEQ/BN, SEQ/BM, BATCH*NHEAD);
        long long so = (long long)SEQ*3*HID, si = HDIM;
        long long sC_o = 8LL*SEQ*SEQ,        sC_i = (long long)SEQ*SEQ;
        gemm_kernel<EPI_SCALE,true,true><<<g,256,SMEM_BYTES>>>(qkv, qkv + HID, nullptr, nullptr, P,
            SEQ, SEQ, HDIM, 3*HID, 3*HID, SEQ,
            so, si, so, si, sC_o, sC_i, SCORE_SCALE);
    }

    // 4) causal softmax
    softmax_kernel<<<dim3(SEQ, BATCH*NHEAD), 256>>>(P);

    // 5) y = P @ V; v at col 2*HID within packed qkv
    {
        dim3 g(1, SEQ/BM, BATCH*NHEAD);
        long long sA_o = 8LL*SEQ*SEQ, sA_i = (long long)SEQ*SEQ;
        long long sB_o = (long long)SEQ*3*HID, sB_i = HDIM;
        long long sC_o = (long long)SEQ*HID,   sC_i = HDIM;
        gemm_kernel<EPI_SCALE,false,true><<<g,256,SMEM_BYTES>>>(P, qkv + 2*HID, nullptr, nullptr, y,
            SEQ, HDIM, SEQ, SEQ, 3*HID, HID,
            sA_o, sA_i, sB_o, sB_i, sC_o, sC_i, 1.f);
    }

    // 6) x2 = x + y @ Wo + bo
    dim3 gP(HID/BN, MTOT/BM, 1);
    gemm_kernel<EPI_BIAS_RES,false,false><<<gP,256,SMEM_BYTES>>>(y, Wo, bo, x, x2,
        MTOT, HID, HID, HID, HID, HID, 0,0, 0,0, 0,0, 1.f);

    // 7) LN2
    ln_kernel<<<MTOT, 256>>>(x2, ln2g, ln2b, h2);

    // 8) m1 = gelu(h2 @ W1 + b1)
    {
        dim3 g(FF/BN, MTOT/BM, 1);
        gemm_kernel<EPI_BIAS_GELU,false,false><<<g,256,SMEM_BYTES>>>(h2, W1, b1, nullptr, m1,
            MTOT, FF, HID, HID, FF, FF, 0,0, 0,0, 0,0, 1.f);
    }

    // 9) out = x2 + m1 @ W2 + b2
    gemm_kernel<EPI_BIAS_RES,false,false><<<gP,256,SMEM_BYTES>>>(m1, W2, b2, x2, out,
        MTOT, HID, FF, FF, HID, HID, 0,0, 0,0, 0,0, 1.f);
}

// round 3
// speedup vs baseline: 1.3053x; 1.0520x over previous
#include <cuda_runtime.h>
#include <mma.h>
#include <math.h>
#include <stdint.h>

using namespace nvcuda;

// ---------------- problem constants ----------------
#define BATCH 2
#define SEQ   2048
#define HID   1024
#define NHEAD 8
#define HDIM  128
#define FF    4096
#define MTOT  (BATCH*SEQ)      // 4096
#define LN_EPS 1e-5f

// ---------------- scratch (static device, no allocs) ----------------
__device__ float g_h   [MTOT*HID];
__device__ float g_qkv [(size_t)MTOT*3*HID];
__device__ float g_y   [MTOT*HID];
__device__ float g_x2  [MTOT*HID];
__device__ float g_h2  [MTOT*HID];
__device__ float g_m1  [(size_t)MTOT*FF];
__device__ float g_p   [(size_t)BATCH*NHEAD*SEQ*SEQ]; // 268 MB scores/probs
__device__ float g_wqkv[(size_t)HID*3*HID];
__device__ float g_bqkv[3*HID];
__device__ float g_wo  [(size_t)HID*HID];
__device__ float g_w1  [(size_t)HID*FF];
__device__ float g_w2  [(size_t)FF*HID];

// ---------------- helpers ----------------
__device__ __forceinline__ float tf32r(float x){ return wmma::__float_to_tf32(x); } // cvt.rna

__device__ __forceinline__ void cp_async16(void* smem_dst, const void* gmem_src){
    uint32_t s = (uint32_t)__cvta_generic_to_shared(smem_dst);
    asm volatile("cp.async.cg.shared.global [%0], [%1], 16;\n" :: "r"(s), "l"(gmem_src));
}
__device__ __forceinline__ void cp_commit(){
    asm volatile("cp.async.commit_group;\n");
}
template<int N>
__device__ __forceinline__ void cp_wait(){
    asm volatile("cp.async.wait_group %0;\n" :: "n"(N));
}

__device__ __forceinline__ float warpSum(float v){
#pragma unroll
    for (int o=16;o;o>>=1) v += __shfl_xor_sync(0xffffffffu, v, o);
    return v;
}
__device__ __forceinline__ float warpMax(float v){
#pragma unroll
    for (int o=16;o;o>>=1) v = fmaxf(v, __shfl_xor_sync(0xffffffffu, v, o));
    return v;
}
__device__ __forceinline__ float blockSum(float v, float* red){
    __syncthreads();
    int lane = threadIdx.x & 31, wid = threadIdx.x >> 5;
    v = warpSum(v);
    if (lane==0) red[wid] = v;
    __syncthreads();
    if (wid==0){
        float r = (lane < (int)(blockDim.x>>5)) ? red[lane] : 0.f;
        r = warpSum(r);
        if (lane==0) red[0] = r;
    }
    __syncthreads();
    return red[0];
}
__device__ __forceinline__ float blockMax(float v, float* red){
    __syncthreads();
    int lane = threadIdx.x & 31, wid = threadIdx.x >> 5;
    v = warpMax(v);
    if (lane==0) red[wid] = v;
    __syncthreads();
    if (wid==0){
        float r = (lane < (int)(blockDim.x>>5)) ? red[lane] : -1e30f;
        r = warpMax(r);
        if (lane==0) red[0] = r;
    }
    __syncthreads();
    return red[0];
}

// ---------------- weight prep ----------------
__global__ void __launch_bounds__(256) pack_qkv_kernel(
    const float* __restrict__ Wq, const float* __restrict__ Wk, const float* __restrict__ Wv,
    const float* __restrict__ bq, const float* __restrict__ bk, const float* __restrict__ bv,
    float* __restrict__ W, float* __restrict__ b)
{
    size_t i = (size_t)blockIdx.x*256 + threadIdx.x;
    size_t total = (size_t)HID*3*HID;
    for (size_t idx = i; idx < total; idx += (size_t)gridDim.x*256){
        size_t k = idx / (3*HID);
        int    n = (int)(idx % (3*HID));
        float v;
        if      (n <   HID) v = Wq[k*HID + n];
        else if (n < 2*HID) v = Wk[k*HID + (n-HID)];
        else                v = Wv[k*HID + (n-2*HID)];
        W[idx] = tf32r(v);
    }
    if (i < 3*HID){
        int n = (int)i;
        b[n] = (n < HID) ? bq[n] : (n < 2*HID ? bk[n-HID] : bv[n-2*HID]);
    }
}

__global__ void __launch_bounds__(256) round_copy_kernel(const float* __restrict__ src,
                                                         float* __restrict__ dst, size_t n)
{
    size_t i = (size_t)blockIdx.x*256 + threadIdx.x;
    for (; i < n; i += (size_t)gridDim.x*256) dst[i] = tf32r(src[i]);
}

// ---------------- layernorm (tf32-rounded output) ----------------
__global__ void __launch_bounds__(256) ln_kernel(const float* __restrict__ x,
                                                 const float* __restrict__ g,
                                                 const float* __restrict__ b,
                                                 float* __restrict__ out)
{
    __shared__ float red[32];
    int row = blockIdx.x;
    const float* xr = x + (size_t)row*HID;
    float v[4];
    float s = 0.f;
#pragma unroll
    for (int t=0;t<4;t++){ v[t] = xr[threadIdx.x + t*256]; s += v[t]; }
    s = blockSum(s, red);
    float mu = s * (1.f/HID);
    float s2 = 0.f;
#pragma unroll
    for (int t=0;t<4;t++){ float d = v[t]-mu; s2 += d*d; }
    s2 = blockSum(s2, red);
    float rstd = rsqrtf(s2*(1.f/HID) + LN_EPS);
    float* orow = out + (size_t)row*HID;
#pragma unroll
    for (int t=0;t<4;t++){
        int c = threadIdx.x + t*256;
        orow[c] = tf32r((v[t]-mu)*rstd*g[c] + b[c]);
    }
}

// ---------------- causal softmax (tf32-rounded output) ----------------
__global__ void __launch_bounds__(256) softmax_kernel(float* __restrict__ P)
{
    __shared__ float red[32];
    int i  = blockIdx.x;
    int bh = blockIdx.y;
    float* row = P + ((size_t)bh*SEQ + i)*SEQ;
    int L    = i + 1;
    int Lpad = ((i>>7)+1)<<7;

    float m = -1e30f;
    for (int j=threadIdx.x; j<L; j+=256) m = fmaxf(m, row[j]);
    m = blockMax(m, red);

    float s = 0.f;
    for (int j=threadIdx.x; j<L; j+=256) s += __expf(row[j]-m);
    s = blockSum(s, red);
    float inv = 1.f/s;

    for (int j=threadIdx.x; j<Lpad; j+=256)
        row[j] = (j < L) ? tf32r(__expf(row[j]-m)*inv) : 0.f;
}

// ---------------- pipelined tf32 tensor-core GEMM ----------------
enum { EPI_SCALE=0, EPI_BIAS=1, EPI_BIAS_RES=2, EPI_BIAS_GELU=3 };

constexpr int BM = 128, BN = 128, BK = 32;
constexpr int STAGES = 3;
constexpr int LDA_S = BK + 4;            // 36
constexpr int LDB_S = BN + 4;            // 132
constexpr int A_STG = BM * LDA_S;        // 4608
constexpr int B_STG = (BK*LDB_S > BM*LDA_S) ? BK*LDB_S : BM*LDA_S; // 4608
constexpr size_t SMEM_BYTES = (size_t)STAGES * (A_STG + B_STG) * 4;  // 110592

template<int EPI, bool BT, bool CAUSAL, bool RND>
__global__ void __launch_bounds__(256, 2) gemm_kernel(
    const float* __restrict__ A, const float* __restrict__ B,
    const float* __restrict__ bias, const float* __restrict__ res,
    float* __restrict__ C,
    int M, int N, int K,
    int lda, int ldb, int ldc,
    long long soA, long long siA,
    long long soB, long long siB,
    long long soC, long long siC,
    float scale)
{
    int bx = blockIdx.x, by = blockIdx.y, bz = blockIdx.z;
    if (CAUSAL && bx > by) return;
    int Keff = K;
    if (CAUSAL){ int kl = (by+1)*BM; if (kl < Keff) Keff = kl; }
    int nk = Keff / BK;

    long long offA = (long long)(bz>>3)*soA + (long long)(bz&7)*siA;
    long long offB = (long long)(bz>>3)*soB + (long long)(bz&7)*siB;
    long long offC = (long long)(bz>>3)*soC + (long long)(bz&7)*siC;
    A += offA; B += offB; C += offC;
    const float* resp = (EPI==EPI_BIAS_RES) ? (res + offC) : nullptr;

    extern __shared__ float smem[];
    float* As = smem;
    float* Bs = smem + (size_t)STAGES * A_STG;

    int tid  = threadIdx.x;
    int wid  = tid >> 5;
    int lane = tid & 31;
    int row0 = by*BM, col0 = bx*BN;
    int wr = (wid>>2)*64;
    int wc = (wid&3)*32;

    wmma::fragment<wmma::accumulator,16,16,8,float> acc[4][2];
#pragma unroll
    for (int i=0;i<4;i++)
#pragma unroll
        for (int j=0;j<2;j++) wmma::fill_fragment(acc[i][j], 0.f);

    auto load_tile = [&](int kt, int buf){
        int k0 = kt*BK;
        float* as = As + buf*A_STG;
        const float* Ab = A + (size_t)row0*lda + k0;
#pragma unroll
        for (int p=0;p<4;p++){
            int c  = tid + p*256;
            int r  = c >> 3;
            int q4 = (c & 7) * 4;
            cp_async16(as + r*LDA_S + q4, Ab + (size_t)r*lda + q4);
        }
        float* bs = Bs + buf*B_STG;
        if (BT){
            const float* Bb = B + (size_t)col0*ldb + k0;
#pragma unroll
            for (int p=0;p<4;p++){
                int c  = tid + p*256;
                int r  = c >> 3;
                int q4 = (c & 7) * 4;
                cp_async16(bs + r*LDA_S + q4, Bb + (size_t)r*ldb + q4);
            }
        } else {
            const float* Bb = B + (size_t)k0*ldb + col0;
#pragma unroll
            for (int p=0;p<4;p++){
                int c  = tid + p*256;
                int r  = c >> 5;
                int q4 = (c & 31) * 4;
                cp_async16(bs + r*LDB_S + q4, Bb + (size_t)r*ldb + q4);
            }
        }
    };

    auto compute = [&](int buf){
        const float* as = As + buf*A_STG;
        const float* bs = Bs + buf*B_STG;
#pragma unroll
        for (int kk=0; kk<BK; kk+=8){
            wmma::fragment<wmma::matrix_a,16,16,8,wmma::precision::tf32,wmma::row_major> af[4];
#pragma unroll
            for (int i=0;i<4;i++)
                wmma::load_matrix_sync(af[i], as + (wr+i*16)*LDA_S + kk, LDA_S);
            if constexpr (BT){
                wmma::fragment<wmma::matrix_b,16,16,8,wmma::precision::tf32,wmma::col_major> bf[2];
#pragma unroll
                for (int j=0;j<2;j++)
                    wmma::load_matrix_sync(bf[j], bs + (wc+j*16)*LDA_S + kk, LDA_S);
#pragma unroll
                for (int i=0;i<4;i++)
#pragma unroll
                    for (int j=0;j<2;j++)
                        wmma::mma_sync(acc[i][j], af[i], bf[j], acc[i][j]);
            } else {
                wmma::fragment<wmma::matrix_b,16,16,8,wmma::precision::tf32,wmma::row_major> bf[2];
#pragma unroll
                for (int j=0;j<2;j++)
                    wmma::load_matrix_sync(bf[j], bs + kk*LDB_S + wc + j*16, LDB_S);
#pragma unroll
                for (int i=0;i<4;i++)
#pragma unroll
                    for (int j=0;j<2;j++)
                        wmma::mma_sync(acc[i][j], af[i], bf[j], acc[i][j]);
            }
        }
    };

#pragma unroll
    for (int s=0; s<STAGES-1; s++){
        if (s < nk) load_tile(s, s);
        cp_commit();
    }

    for (int kt=0; kt<nk; kt++){
        cp_wait<STAGES-2>();
        __syncthreads();
        int pre = kt + STAGES - 1;
        if (pre < nk) load_tile(pre, pre % STAGES);
        cp_commit();
        compute(kt % STAGES);
    }

    __syncthreads();
    float* epi = smem + (size_t)wid * 320;
#pragma unroll
    for (int i=0;i<4;i++){
#pragma unroll
        for (int j=0;j<2;j++){
            wmma::store_matrix_sync(epi, acc[i][j], 20, wmma::mem_row_major);
            __syncwarp();
#pragma unroll
            for (int e=lane; e<256; e+=32){
                int r  = e >> 4, cc = e & 15;
                int gr = row0 + wr + i*16 + r;
                int gc = col0 + wc + j*16 + cc;
                float v = epi[r*20 + cc] * scale;
                if (EPI >= EPI_BIAS)      v += bias[gc];
                if (EPI == EPI_BIAS_RES)  v += resp[(size_t)gr*ldc + gc];
                if (EPI == EPI_BIAS_GELU) v = 0.5f*v*(1.f + erff(v*0.70710678118654752f));
                if (RND)                  v = tf32r(v);
                C[(size_t)gr*ldc + gc] = v;
            }
            __syncwarp();
        }
    }
}

// ---------------- launch ----------------
extern "C" void kernel_launch(void* const* d_in, const int* in_sizes, int n_in,
                              void* d_out, int out_size)
{
    const float* x    = (const float*)d_in[0];
    const float* ln1g = (const float*)d_in[1];
    const float* ln1b = (const float*)d_in[2];
    const float* ln2g = (const float*)d_in[3];
    const float* ln2b = (const float*)d_in[4];
    const float* Wq   = (const float*)d_in[5];
    const float* bq   = (const float*)d_in[6];
    const float* Wk   = (const float*)d_in[7];
    const float* bk   = (const float*)d_in[8];
    const float* Wv   = (const float*)d_in[9];
    const float* bv   = (const float*)d_in[10];
    const float* Wo   = (const float*)d_in[11];
    const float* bo   = (const float*)d_in[12];
    const float* W1   = (const float*)d_in[13];
    const float* b1   = (const float*)d_in[14];
    const float* W2   = (const float*)d_in[15];
    const float* b2   = (const float*)d_in[16];
    float* out = (float*)d_out;

    void *ph, *pqkv, *py, *px2, *ph2, *pm1, *pp, *pw, *pb, *pwo, *pw1, *pw2;
    cudaGetSymbolAddress(&ph,   g_h);
    cudaGetSymbolAddress(&pqkv, g_qkv);
    cudaGetSymbolAddress(&py,   g_y);
    cudaGetSymbolAddress(&px2,  g_x2);
    cudaGetSymbolAddress(&ph2,  g_h2);
    cudaGetSymbolAddress(&pm1,  g_m1);
    cudaGetSymbolAddress(&pp,   g_p);
    cudaGetSymbolAddress(&pw,   g_wqkv);
    cudaGetSymbolAddress(&pb,   g_bqkv);
    cudaGetSymbolAddress(&pwo,  g_wo);
    cudaGetSymbolAddress(&pw1,  g_w1);
    cudaGetSymbolAddress(&pw2,  g_w2);
    float* h   = (float*)ph;   float* qkv = (float*)pqkv;
    float* y   = (float*)py;   float* x2  = (float*)px2;
    float* h2  = (float*)ph2;  float* m1  = (float*)pm1;
    float* P   = (float*)pp;   float* Wqkv= (float*)pw;  float* bqkv = (float*)pb;
    float* WoR = (float*)pwo;  float* W1R = (float*)pw1; float* W2R  = (float*)pw2;

    static bool attr_done = false;
    if (!attr_done){
        cudaFuncSetAttribute(gemm_kernel<EPI_BIAS,false,false,true>,       cudaFuncAttributeMaxDynamicSharedMemorySize, (int)SMEM_BYTES);
        cudaFuncSetAttribute(gemm_kernel<EPI_SCALE,true,true,false>,       cudaFuncAttributeMaxDynamicSharedMemorySize, (int)SMEM_BYTES);
        cudaFuncSetAttribute(gemm_kernel<EPI_SCALE,false,true,true>,       cudaFuncAttributeMaxDynamicSharedMemorySize, (int)SMEM_BYTES);
        cudaFuncSetAttribute(gemm_kernel<EPI_BIAS_RES,false,false,false>,  cudaFuncAttributeMaxDynamicSharedMemorySize, (int)SMEM_BYTES);
        cudaFuncSetAttribute(gemm_kernel<EPI_BIAS_GELU,false,false,true>,  cudaFuncAttributeMaxDynamicSharedMemorySize, (int)SMEM_BYTES);
        attr_done = true;
    }

    const float SCORE_SCALE = 0.08838834764831845f; // 1/sqrt(128)

    // 0) weight prep: pack+round QKV, round Wo/W1/W2
    pack_qkv_kernel<<<1024, 256>>>(Wq, Wk, Wv, bq, bk, bv, Wqkv, bqkv);
    round_copy_kernel<<<512, 256>>>(Wo, WoR, (size_t)HID*HID);
    round_copy_kernel<<<2048, 256>>>(W1, W1R, (size_t)HID*FF);
    round_copy_kernel<<<2048, 256>>>(W2, W2R, (size_t)FF*HID);

    // 1) LN1
    ln_kernel<<<MTOT, 256>>>(x, ln1g, ln1b, h);

    // 2) packed QKV projection
    {
        dim3 g(3*HID/BN, MTOT/BM, 1);
        gemm_kernel<EPI_BIAS,false,false,true><<<g,256,SMEM_BYTES>>>(h, Wqkv, bqkv, nullptr, qkv,
            MTOT, 3*HID, HID, HID, 3*HID, 3*HID, 0,0, 0,0, 0,0, 1.f);
    }

    // 3) scores = q @ k^T / sqrt(HD)
    {
        dim3 g(SEQ/BN, SEQ/BM, BATCH*NHEAD);
        long long so = (long long)SEQ*3*HID, si = HDIM;
        long long sC_o = 8LL*SEQ*SEQ,        sC_i = (long long)SEQ*SEQ;
        gemm_kernel<EPI_SCALE,true,true,false><<<g,256,SMEM_BYTES>>>(qkv, qkv + HID, nullptr, nullptr, P,
            SEQ, SEQ, HDIM, 3*HID, 3*HID, SEQ,
            so, si, so, si, sC_o, sC_i, SCORE_SCALE);
    }

    // 4) causal softmax
    softmax_kernel<<<dim3(SEQ, BATCH*NHEAD), 256>>>(P);

    // 5) y = P @ V
    {
        dim3 g(1, SEQ/BM, BATCH*NHEAD);
        long long sA_o = 8LL*SEQ*SEQ, sA_i = (long long)SEQ*SEQ;
        long long sB_o = (long long)SEQ*3*HID, sB_i = HDIM;
        long long sC_o = (long long)SEQ*HID,   sC_i = HDIM;
        gemm_kernel<EPI_SCALE,false,true,true><<<g,256,SMEM_BYTES>>>(P, qkv + 2*HID, nullptr, nullptr, y,
            SEQ, HDIM, SEQ, SEQ, 3*HID, HID,
            sA_o, sA_i, sB_o, sB_i, sC_o, sC_i, 1.f);
    }

    // 6) x2 = x + y @ Wo + bo   (fp32 output, no rounding)
    dim3 gP(HID/BN, MTOT/BM, 1);
    gemm_kernel<EPI_BIAS_RES,false,false,false><<<gP,256,SMEM_BYTES>>>(y, WoR, bo, x, x2,
        MTOT, HID, HID, HID, HID, HID, 0,0, 0,0, 0,0, 1.f);

    // 7) LN2
    ln_kernel<<<MTOT, 256>>>(x2, ln2g, ln2b, h2);

    // 8) m1 = gelu(h2 @ W1 + b1)
    {
        dim3 g(FF/BN, MTOT/BM, 1);
        gemm_kernel<EPI_BIAS_GELU,false,false,true><<<g,256,SMEM_BYTES>>>(h2, W1R, b1, nullptr, m1,
            MTOT, FF, HID, HID, FF, FF, 0,0, 0,0, 0,0, 1.f);
    }

    // 9) out = x2 + m1 @ W2 + b2   (fp32 output, no rounding)
    gemm_kernel<EPI_BIAS_RES,false,false,false><<<gP,256,SMEM_BYTES>>>(m1, W2R, b2, x2, out,
        MTOT, HID, FF, FF, HID, HID, 0,0, 0,0, 0,0, 1.f);
}

// round 4
// speedup vs baseline: 1.3285x; 1.0178x over previous
#include <cuda_runtime.h>
#include <mma.h>
#include <math.h>
#include <stdint.h>

using namespace nvcuda;

// ---------------- problem constants ----------------
#define BATCH 2
#define SEQ   2048
#define HID   1024
#define NHEAD 8
#define HDIM  128
#define FF    4096
#define MTOT  (BATCH*SEQ)      // 4096
#define LN_EPS 1e-5f

// ---------------- scratch (static device, no allocs) ----------------
__device__ float g_h   [MTOT*HID];
__device__ float g_qkv [(size_t)MTOT*3*HID];
__device__ float g_y   [MTOT*HID];
__device__ float g_x2  [MTOT*HID];
__device__ float g_h2  [MTOT*HID];
__device__ float g_m1  [(size_t)MTOT*FF];
__device__ float g_wqkv[(size_t)HID*3*HID];
__device__ float g_bqkv[3*HID];
__device__ float g_wo  [(size_t)HID*HID];
__device__ float g_w1  [(size_t)HID*FF];
__device__ float g_w2  [(size_t)FF*HID];

// ---------------- helpers ----------------
__device__ __forceinline__ float tf32r(float x){ return wmma::__float_to_tf32(x); } // cvt.rna

__device__ __forceinline__ void cp_async16(void* smem_dst, const void* gmem_src){
    uint32_t s = (uint32_t)__cvta_generic_to_shared(smem_dst);
    asm volatile("cp.async.cg.shared.global [%0], [%1], 16;\n" :: "r"(s), "l"(gmem_src));
}
__device__ __forceinline__ void cp_commit(){
    asm volatile("cp.async.commit_group;\n");
}
template<int N>
__device__ __forceinline__ void cp_wait(){
    asm volatile("cp.async.wait_group %0;\n" :: "n"(N));
}

__device__ __forceinline__ float warpSum(float v){
#pragma unroll
    for (int o=16;o;o>>=1) v += __shfl_xor_sync(0xffffffffu, v, o);
    return v;
}
__device__ __forceinline__ float blockSum(float v, float* red){
    __syncthreads();
    int lane = threadIdx.x & 31, wid = threadIdx.x >> 5;
    v = warpSum(v);
    if (lane==0) red[wid] = v;
    __syncthreads();
    if (wid==0){
        float r = (lane < (int)(blockDim.x>>5)) ? red[lane] : 0.f;
        r = warpSum(r);
        if (lane==0) red[0] = r;
    }
    __syncthreads();
    return red[0];
}

// ---------------- weight prep ----------------
__global__ void __launch_bounds__(256) pack_qkv_kernel(
    const float* __restrict__ Wq, const float* __restrict__ Wk, const float* __restrict__ Wv,
    const float* __restrict__ bq, const float* __restrict__ bk, const float* __restrict__ bv,
    float* __restrict__ W, float* __restrict__ b)
{
    size_t i = (size_t)blockIdx.x*256 + threadIdx.x;
    size_t total = (size_t)HID*3*HID;
    for (size_t idx = i; idx < total; idx += (size_t)gridDim.x*256){
        size_t k = idx / (3*HID);
        int    n = (int)(idx % (3*HID));
        float v;
        if      (n <   HID) v = Wq[k*HID + n];
        else if (n < 2*HID) v = Wk[k*HID + (n-HID)];
        else                v = Wv[k*HID + (n-2*HID)];
        W[idx] = tf32r(v);
    }
    if (i < 3*HID){
        int n = (int)i;
        b[n] = (n < HID) ? bq[n] : (n < 2*HID ? bk[n-HID] : bv[n-2*HID]);
    }
}

__global__ void __launch_bounds__(256) round_copy_kernel(const float* __restrict__ src,
                                                         float* __restrict__ dst, size_t n)
{
    size_t i = (size_t)blockIdx.x*256 + threadIdx.x;
    for (; i < n; i += (size_t)gridDim.x*256) dst[i] = tf32r(src[i]);
}

// ---------------- layernorm (tf32-rounded output) ----------------
__global__ void __launch_bounds__(256) ln_kernel(const float* __restrict__ x,
                                                 const float* __restrict__ g,
                                                 const float* __restrict__ b,
                                                 float* __restrict__ out)
{
    __shared__ float red[32];
    int row = blockIdx.x;
    const float* xr = x + (size_t)row*HID;
    float v[4];
    float s = 0.f;
#pragma unroll
    for (int t=0;t<4;t++){ v[t] = xr[threadIdx.x + t*256]; s += v[t]; }
    s = blockSum(s, red);
    float mu = s * (1.f/HID);
    float s2 = 0.f;
#pragma unroll
    for (int t=0;t<4;t++){ float d = v[t]-mu; s2 += d*d; }
    s2 = blockSum(s2, red);
    float rstd = rsqrtf(s2*(1.f/HID) + LN_EPS);
    float* orow = out + (size_t)row*HID;
#pragma unroll
    for (int t=0;t<4;t++){
        int c = threadIdx.x + t*256;
        orow[c] = tf32r((v[t]-mu)*rstd*g[c] + b[c]);
    }
}

// ---------------- fused flash attention ----------------
// grid: (SEQ/64, BATCH*NHEAD), 256 threads.
// Each CTA: 64 q rows of one (b,head); loops over 64-row KV tiles (causal),
// cp.async double-buffered; online softmax with O accumulator in smem.
constexpr int FQ = 64, FK = 64;
constexpr int LDQ = 132, LDK = 132, LDV = 132, LDSS = 68, LDO = 132;
constexpr int OFF_Q = 0;
constexpr int OFF_K = OFF_Q + FQ*LDQ;           // Q: 64x132
constexpr int OFF_V = OFF_K + 2*FK*LDK;         // K: 2 bufs 64x132
constexpr int OFF_S = OFF_V + 2*FK*LDV;         // V: 2 bufs 64x132
constexpr int OFF_O = OFF_S + FQ*LDSS;          // S/P: 64x68
constexpr int OFF_M = OFF_O + FQ*LDO;           // O: 64x132
constexpr int OFF_L = OFF_M + FQ;
constexpr size_t FLASH_SMEM = (size_t)(OFF_L + FQ) * 4;

__global__ void __launch_bounds__(256, 1) flash_kernel(
    const float* __restrict__ qkv, float* __restrict__ y)
{
    extern __shared__ float sm[];
    const float SCORE_SCALE = 0.08838834764831845f; // 1/sqrt(128)

    int qi   = (int)gridDim.x - 1 - (int)blockIdx.x;   // heavy tiles first
    int b    = blockIdx.y >> 3;
    int head = blockIdx.y & 7;
    int tid  = threadIdx.x;
    int wid  = tid >> 5;

    const float* base = qkv + (size_t)b*SEQ*3*HID + head*HDIM;

    auto loadQ = [&](){
        const float* src = base + (size_t)(64*qi)*3*HID;
#pragma unroll
        for (int p=0;p<8;p++){
            int c = tid + p*256;
            int r = c >> 5;
            int f = (c & 31) * 4;
            cp_async16(&sm[OFF_Q + r*LDQ + f], src + (size_t)r*3*HID + f);
        }
    };
    auto loadK = [&](int t, int buf){
        const float* src = base + HID + (size_t)(64*t)*3*HID;
        float* dst = &sm[OFF_K + buf*FK*LDK];
#pragma unroll
        for (int p=0;p<8;p++){
            int c = tid + p*256;
            int r = c >> 5;
            int f = (c & 31) * 4;
            cp_async16(dst + r*LDK + f, src + (size_t)r*3*HID + f);
        }
    };
    auto loadV = [&](int t, int buf){
        const float* src = base + 2*HID + (size_t)(64*t)*3*HID;
        float* dst = &sm[OFF_V + buf*FK*LDV];
#pragma unroll
        for (int p=0;p<8;p++){
            int c = tid + p*256;
            int r = c >> 5;
            int f = (c & 31) * 4;
            cp_async16(dst + r*LDV + f, src + (size_t)r*3*HID + f);
        }
    };

    loadQ(); loadK(0,0); loadV(0,0); cp_commit();

    // init O accumulator + row stats
    for (int i=tid; i<FQ*LDO; i+=256) sm[OFF_O + i] = 0.f;
    if (tid < FQ){ sm[OFF_M + tid] = -1e30f; sm[OFF_L + tid] = 0.f; }

    int nkv = qi + 1;
    int wrS = (wid>>2)*32, wcS = (wid&3)*16;   // S gemm: 32x16 per warp
    int wrP = (wid>>2)*32, wcP = (wid&3)*32;   // PV gemm: 32x32 per warp
    int srow = tid >> 2, sl = tid & 3;         // stats: 4 threads per row

    for (int t=0; t<nkv; t++){
        int buf = t & 1;
        if (t+1 < nkv){ loadK(t+1, buf^1); loadV(t+1, buf^1); cp_commit(); cp_wait<1>(); }
        else          { cp_wait<0>(); }
        __syncthreads();

        // ---- S = Q @ K^T * scale ----
        {
            wmma::fragment<wmma::accumulator,16,16,8,float> s[2];
#pragma unroll
            for (int i=0;i<2;i++) wmma::fill_fragment(s[i], 0.f);
            const float* kb = &sm[OFF_K + buf*FK*LDK];
#pragma unroll
            for (int kk=0; kk<HDIM; kk+=8){
                wmma::fragment<wmma::matrix_a,16,16,8,wmma::precision::tf32,wmma::row_major> af[2];
#pragma unroll
                for (int i=0;i<2;i++)
                    wmma::load_matrix_sync(af[i], &sm[OFF_Q + (wrS+i*16)*LDQ + kk], LDQ);
                wmma::fragment<wmma::matrix_b,16,16,8,wmma::precision::tf32,wmma::col_major> bf;
                wmma::load_matrix_sync(bf, kb + wcS*LDK + kk, LDK);
#pragma unroll
                for (int i=0;i<2;i++)
                    wmma::mma_sync(s[i], af[i], bf, s[i]);
            }
#pragma unroll
            for (int i=0;i<2;i++){
#pragma unroll
                for (int e=0; e<s[i].num_elements; e++) s[i].x[e] *= SCORE_SCALE;
                wmma::store_matrix_sync(&sm[OFF_S + (wrS+i*16)*LDSS + wcS], s[i], LDSS, wmma::mem_row_major);
            }
        }
        __syncthreads();

        // ---- online softmax: stats + P + O rescale ----
        {
            float* Srow = &sm[OFF_S + srow*LDSS];
            bool maskt = (t == qi);
            float vbuf[16];
            float mx = -1e30f;
#pragma unroll
            for (int j=0;j<16;j++){
                int c = sl + 4*j;
                float v = Srow[c];
                if (maskt && c > srow) v = -1e30f;
                vbuf[j] = v;
                mx = fmaxf(mx, v);
            }
            mx = fmaxf(mx, __shfl_xor_sync(0xffffffffu, mx, 1));
            mx = fmaxf(mx, __shfl_xor_sync(0xffffffffu, mx, 2));
            float mold = sm[OFF_M + srow];
            float newm = fmaxf(mold, mx);
            float ps = 0.f;
#pragma unroll
            for (int j=0;j<16;j++){
                int c = sl + 4*j;
                float p = __expf(vbuf[j] - newm);
                ps += p;
                Srow[c] = tf32r(p);
            }
            ps += __shfl_xor_sync(0xffffffffu, ps, 1);
            ps += __shfl_xor_sync(0xffffffffu, ps, 2);
            float alpha = __expf(mold - newm);
            if (sl == 0){
                sm[OFF_M + srow] = newm;
                sm[OFF_L + srow] = sm[OFF_L + srow]*alpha + ps;
            }
            float* Orow = &sm[OFF_O + srow*LDO];
#pragma unroll
            for (int j=0;j<32;j++){
                int c = sl + 4*j;
                Orow[c] *= alpha;
            }
        }
        __syncthreads();

        // ---- O += P @ V ----
        {
            wmma::fragment<wmma::accumulator,16,16,8,float> o[2][2];
#pragma unroll
            for (int i=0;i<2;i++)
#pragma unroll
                for (int j=0;j<2;j++)
                    wmma::load_matrix_sync(o[i][j], &sm[OFF_O + (wrP+i*16)*LDO + wcP + j*16], LDO, wmma::mem_row_major);
            const float* vb = &sm[OFF_V + buf*FK*LDV];
#pragma unroll
            for (int kk=0; kk<FK; kk+=8){
                wmma::fragment<wmma::matrix_a,16,16,8,wmma::precision::tf32,wmma::row_major> af[2];
#pragma unroll
                for (int i=0;i<2;i++)
                    wmma::load_matrix_sync(af[i], &sm[OFF_S + (wrP+i*16)*LDSS + kk], LDSS);
                wmma::fragment<wmma::matrix_b,16,16,8,wmma::precision::tf32,wmma::row_major> bf[2];
#pragma unroll
                for (int j=0;j<2;j++)
                    wmma::load_matrix_sync(bf[j], vb + kk*LDV + wcP + j*16, LDV);
#pragma unroll
                for (int i=0;i<2;i++)
#pragma unroll
                    for (int j=0;j<2;j++)
                        wmma::mma_sync(o[i][j], af[i], bf[j], o[i][j]);
            }
#pragma unroll
            for (int i=0;i<2;i++)
#pragma unroll
                for (int j=0;j<2;j++)
                    wmma::store_matrix_sync(&sm[OFF_O + (wrP+i*16)*LDO + wcP + j*16], o[i][j], LDO, wmma::mem_row_major);
        }
        __syncthreads();
    }

    // ---- epilogue: y = O / l  (tf32-rounded; feeds O-proj GEMM) ----
    {
        float invl = 1.f / sm[OFF_L + srow];
        float* Orow = &sm[OFF_O + srow*LDO];
        float* dst = y + ((size_t)(b*SEQ + 64*qi + srow))*HID + head*HDIM;
#pragma unroll
        for (int j=0;j<32;j++){
            int c = sl + 4*j;
            dst[c] = tf32r(Orow[c] * invl);
        }
    }
}

// ---------------- pipelined tf32 tensor-core GEMM ----------------
enum { EPI_SCALE=0, EPI_BIAS=1, EPI_BIAS_RES=2, EPI_BIAS_GELU=3 };

constexpr int BM = 128, BN = 128, BK = 32;
constexpr int STAGES = 3;
constexpr int LDA_S = BK + 4;            // 36
constexpr int LDB_S = BN + 4;            // 132
constexpr int A_STG = BM * LDA_S;        // 4608
constexpr int B_STG = (BK*LDB_S > BM*LDA_S) ? BK*LDB_S : BM*LDA_S; // 4608
constexpr size_t SMEM_BYTES = (size_t)STAGES * (A_STG + B_STG) * 4;  // 110592

template<int EPI, bool BT, bool CAUSAL, bool RND>
__global__ void __launch_bounds__(256, 2) gemm_kernel(
    const float* __restrict__ A, const float* __restrict__ B,
    const float* __restrict__ bias, const float* __restrict__ res,
    float* __restrict__ C,
    int M, int N, int K,
    int lda, int ldb, int ldc,
    long long soA, long long siA,
    long long soB, long long siB,
    long long soC, long long siC,
    float scale)
{
    int bx = blockIdx.x, by = blockIdx.y, bz = blockIdx.z;
    if (CAUSAL && bx > by) return;
    int Keff = K;
    if (CAUSAL){ int kl = (by+1)*BM; if (kl < Keff) Keff = kl; }
    int nk = Keff / BK;

    long long offA = (long long)(bz>>3)*soA + (long long)(bz&7)*siA;
    long long offB = (long long)(bz>>3)*soB + (long long)(bz&7)*siB;
    long long offC = (long long)(bz>>3)*soC + (long long)(bz&7)*siC;
    A += offA; B += offB; C += offC;
    const float* resp = (EPI==EPI_BIAS_RES) ? (res + offC) : nullptr;

    extern __shared__ float smem[];
    float* As = smem;
    float* Bs = smem + (size_t)STAGES * A_STG;

    int tid  = threadIdx.x;
    int wid  = tid >> 5;
    int lane = tid & 31;
    int row0 = by*BM, col0 = bx*BN;
    int wr = (wid>>2)*64;
    int wc = (wid&3)*32;

    wmma::fragment<wmma::accumulator,16,16,8,float> acc[4][2];
#pragma unroll
    for (int i=0;i<4;i++)
#pragma unroll
        for (int j=0;j<2;j++) wmma::fill_fragment(acc[i][j], 0.f);

    auto load_tile = [&](int kt, int bufi){
        int k0 = kt*BK;
        float* as = As + bufi*A_STG;
        const float* Ab = A + (size_t)row0*lda + k0;
#pragma unroll
        for (int p=0;p<4;p++){
            int c  = tid + p*256;
            int r  = c >> 3;
            int q4 = (c & 7) * 4;
            cp_async16(as + r*LDA_S + q4, Ab + (size_t)r*lda + q4);
        }
        float* bs = Bs + bufi*B_STG;
        if (BT){
            const float* Bb = B + (size_t)col0*ldb + k0;
#pragma unroll
            for (int p=0;p<4;p++){
                int c  = tid + p*256;
                int r  = c >> 3;
                int q4 = (c & 7) * 4;
                cp_async16(bs + r*LDA_S + q4, Bb + (size_t)r*ldb + q4);
            }
        } else {
            const float* Bb = B + (size_t)k0*ldb + col0;
#pragma unroll
            for (int p=0;p<4;p++){
                int c  = tid + p*256;
                int r  = c >> 5;
                int q4 = (c & 31) * 4;
                cp_async16(bs + r*LDB_S + q4, Bb + (size_t)r*ldb + q4);
            }
        }
    };

    auto compute = [&](int bufi){
        const float* as = As + bufi*A_STG;
        const float* bs = Bs + bufi*B_STG;
#pragma unroll
        for (int kk=0; kk<BK; kk+=8){
            wmma::fragment<wmma::matrix_a,16,16,8,wmma::precision::tf32,wmma::row_major> af[4];
#pragma unroll
            for (int i=0;i<4;i++)
                wmma::load_matrix_sync(af[i], as + (wr+i*16)*LDA_S + kk, LDA_S);
            if constexpr (BT){
                wmma::fragment<wmma::matrix_b,16,16,8,wmma::precision::tf32,wmma::col_major> bf[2];
#pragma unroll
                for (int j=0;j<2;j++)
                    wmma::load_matrix_sync(bf[j], bs + (wc+j*16)*LDA_S + kk, LDA_S);
#pragma unroll
                for (int i=0;i<4;i++)
#pragma unroll
                    for (int j=0;j<2;j++)
                        wmma::mma_sync(acc[i][j], af[i], bf[j], acc[i][j]);
            } else {
                wmma::fragment<wmma::matrix_b,16,16,8,wmma::precision::tf32,wmma::row_major> bf[2];
#pragma unroll
                for (int j=0;j<2;j++)
                    wmma::load_matrix_sync(bf[j], bs + kk*LDB_S + wc + j*16, LDB_S);
#pragma unroll
                for (int i=0;i<4;i++)
#pragma unroll
                    for (int j=0;j<2;j++)
                        wmma::mma_sync(acc[i][j], af[i], bf[j], acc[i][j]);
            }
        }
    };

#pragma unroll
    for (int s=0; s<STAGES-1; s++){
        if (s < nk) load_tile(s, s);
        cp_commit();
    }

    for (int kt=0; kt<nk; kt++){
        cp_wait<STAGES-2>();
        __syncthreads();
        int pre = kt + STAGES - 1;
        if (pre < nk) load_tile(pre, pre % STAGES);
        cp_commit();
        compute(kt % STAGES);
    }

    __syncthreads();
    float* epi = smem + (size_t)wid * 320;
#pragma unroll
    for (int i=0;i<4;i++){
#pragma unroll
        for (int j=0;j<2;j++){
            wmma::store_matrix_sync(epi, acc[i][j], 20, wmma::mem_row_major);
            __syncwarp();
#pragma unroll
            for (int e=lane; e<256; e+=32){
                int r  = e >> 4, cc = e & 15;
                int gr = row0 + wr + i*16 + r;
                int gc = col0 + wc + j*16 + cc;
                float v = epi[r*20 + cc] * scale;
                if (EPI >= EPI_BIAS)      v += bias[gc];
                if (EPI == EPI_BIAS_RES)  v += resp[(size_t)gr*ldc + gc];
                if (EPI == EPI_BIAS_GELU) v = 0.5f*v*(1.f + erff(v*0.70710678118654752f));
                if (RND)                  v = tf32r(v);
                C[(size_t)gr*ldc + gc] = v;
            }
            __syncwarp();
        }
    }
}

// ---------------- launch ----------------
extern "C" void kernel_launch(void* const* d_in, const int* in_sizes, int n_in,
                              void* d_out, int out_size)
{
    const float* x    = (const float*)d_in[0];
    const float* ln1g = (const float*)d_in[1];
    const float* ln1b = (const float*)d_in[2];
    const float* ln2g = (const float*)d_in[3];
    const float* ln2b = (const float*)d_in[4];
    const float* Wq   = (const float*)d_in[5];
    const float* bq   = (const float*)d_in[6];
    const float* Wk   = (const float*)d_in[7];
    const float* bk   = (const float*)d_in[8];
    const float* Wv   = (const float*)d_in[9];
    const float* bv   = (const float*)d_in[10];
    const float* Wo   = (const float*)d_in[11];
    const float* bo   = (const float*)d_in[12];
    const float* W1   = (const float*)d_in[13];
    const float* b1   = (const float*)d_in[14];
    const float* W2   = (const float*)d_in[15];
    const float* b2   = (const float*)d_in[16];
    float* out = (float*)d_out;

    void *ph, *pqkv, *py, *px2, *ph2, *pm1, *pw, *pb, *pwo, *pw1, *pw2;
    cudaGetSymbolAddress(&ph,   g_h);
    cudaGetSymbolAddress(&pqkv, g_qkv);
    cudaGetSymbolAddress(&py,   g_y);
    cudaGetSymbolAddress(&px2,  g_x2);
    cudaGetSymbolAddress(&ph2,  g_h2);
    cudaGetSymbolAddress(&pm1,  g_m1);
    cudaGetSymbolAddress(&pw,   g_wqkv);
    cudaGetSymbolAddress(&pb,   g_bqkv);
    cudaGetSymbolAddress(&pwo,  g_wo);
    cudaGetSymbolAddress(&pw1,  g_w1);
    cudaGetSymbolAddress(&pw2,  g_w2);
    float* h   = (float*)ph;   float* qkv = (float*)pqkv;
    float* y   = (float*)py;   float* x2  = (float*)px2;
    float* h2  = (float*)ph2;  float* m1  = (float*)pm1;
    float* Wqkv= (float*)pw;   float* bqkv= (float*)pb;
    float* WoR = (float*)pwo;  float* W1R = (float*)pw1; float* W2R = (float*)pw2;

    static bool attr_done = false;
    if (!attr_done){
        cudaFuncSetAttribute(gemm_kernel<EPI_BIAS,false,false,true>,       cudaFuncAttributeMaxDynamicSharedMemorySize, (int)SMEM_BYTES);
        cudaFuncSetAttribute(gemm_kernel<EPI_BIAS_RES,false,false,false>,  cudaFuncAttributeMaxDynamicSharedMemorySize, (int)SMEM_BYTES);
        cudaFuncSetAttribute(gemm_kernel<EPI_BIAS_GELU,false,false,true>,  cudaFuncAttributeMaxDynamicSharedMemorySize, (int)SMEM_BYTES);
        cudaFuncSetAttribute(flash_kernel,                                 cudaFuncAttributeMaxDynamicSharedMemorySize, (int)FLASH_SMEM);
        attr_done = true;
    }

    // 0) weight prep: pack+round QKV, round Wo/W1/W2
    pack_qkv_kernel<<<1024, 256>>>(Wq, Wk, Wv, bq, bk, bv, Wqkv, bqkv);
    round_copy_kernel<<<512, 256>>>(Wo, WoR, (size_t)HID*HID);
    round_copy_kernel<<<2048, 256>>>(W1, W1R, (size_t)HID*FF);
    round_copy_kernel<<<2048, 256>>>(W2, W2R, (size_t)FF*HID);

    // 1) LN1
    ln_kernel<<<MTOT, 256>>>(x, ln1g, ln1b, h);

    // 2) packed QKV projection (tf32-rounded output)
    {
        dim3 g(3*HID/BN, MTOT/BM, 1);
        gemm_kernel<EPI_BIAS,false,false,true><<<g,256,SMEM_BYTES>>>(h, Wqkv, bqkv, nullptr, qkv,
            MTOT, 3*HID, HID, HID, 3*HID, 3*HID, 0,0, 0,0, 0,0, 1.f);
    }

    // 3) fused flash attention -> y
    {
        dim3 g(SEQ/FQ, BATCH*NHEAD);
        flash_kernel<<<g, 256, FLASH_SMEM>>>(qkv, y);
    }

    // 4) x2 = x + y @ Wo + bo
    dim3 gP(HID/BN, MTOT/BM, 1);
    gemm_kernel<EPI_BIAS_RES,false,false,false><<<gP,256,SMEM_BYTES>>>(y, WoR, bo, x, x2,
        MTOT, HID, HID, HID, HID, HID, 0,0, 0,0, 0,0, 1.f);

    // 5) LN2
    ln_kernel<<<MTOT, 256>>>(x2, ln2g, ln2b, h2);

    // 6) m1 = gelu(h2 @ W1 + b1)
    {
        dim3 g(FF/BN, MTOT/BM, 1);
        gemm_kernel<EPI_BIAS_GELU,false,false,true><<<g,256,SMEM_BYTES>>>(h2, W1R, b1, nullptr, m1,
            MTOT, FF, HID, HID, FF, FF, 0,0, 0,0, 0,0, 1.f);
    }

    // 7) out = x2 + m1 @ W2 + b2
    gemm_kernel<EPI_BIAS_RES,false,false,false><<<gP,256,SMEM_BYTES>>>(m1, W2R, b2, x2, out,
        MTOT, HID, FF, FF, HID, HID, 0,0, 0,0, 0,0, 1.f);
}